// round 12
// baseline (speedup 1.0000x reference)
#include <cuda_runtime.h>
#include <cuda_bf16.h>
#include <math.h>
#include <stdint.h>

#define BATCH 64
#define NS 4096
#define CPB 16           // CTAs per batch
#define NPART 13
#define BN (BATCH*NS)

// scratch (device globals; no allocations allowed)
__device__ float g_h [BN];
__device__ float g_da[BN];
__device__ float g_db[BN];
__device__ float g_part[BATCH][CPB][NPART];
__device__ float g_c01[BATCH*2];

// ---------------- smem layout (bytes) ----------------
#define OFF_BHI   0        // W2^T hi: 128 n-rows x 256B, pair-permuted k (32KB)
#define OFF_BLO   32768    // (32KB)
#define OFF_W1C   65536    // 128 x float4 (wa, wb, b1, wd)  (2KB)
#define OFF_B2S   67584
#define OFF_W3S   68096
#define OFF_WPART 68608    // 8 warps x 13 floats
#define SMEMSZ    69120

__device__ __forceinline__ void gelu3f(float x, float& v, float& d1, float& d2) {
    float Phi = normcdff(x);
    float ph  = 0.3989422804014326779f * __expf(-0.5f * x * x);
    v  = x * Phi;
    d1 = fmaf(x, ph, Phi);
    d2 = (2.0f - x * x) * ph;
}
__device__ __forceinline__ uint32_t cvt2(float hi, float lo) {
    uint32_t r;
    asm("cvt.rn.bf16x2.f32 %0, %1, %2;" : "=r"(r) : "f"(hi), "f"(lo));
    return r;
}
// residual pack: h holds bf16x2(hi=e1, lo=e0); return bf16x2 of residuals
__device__ __forceinline__ uint32_t lo2(uint32_t h, float e0, float e1) {
    const float f0 = __uint_as_float(h << 16);
    const float f1 = __uint_as_float(h & 0xffff0000u);
    return cvt2(e1 - f1, e0 - f0);
}
__device__ __forceinline__ void mma16816(float* d, uint32_t a0, uint32_t a1,
                                         uint32_t a2, uint32_t a3,
                                         uint32_t b0, uint32_t b1) {
    asm volatile(
        "mma.sync.aligned.m16n8k16.row.col.f32.bf16.bf16.f32 "
        "{%0,%1,%2,%3}, {%4,%5,%6,%7}, {%8,%9}, {%0,%1,%2,%3};"
        : "+f"(d[0]), "+f"(d[1]), "+f"(d[2]), "+f"(d[3])
        : "r"(a0), "r"(a1), "r"(a2), "r"(a3), "r"(b0), "r"(b1));
}

// ---------------------------------------------------------------------------
// Pass A (mma.sync, register-resident A): grid (CPB, BATCH), 256 thr, 8 warps.
// Warp-iter: 4 sites (16 rows = 4 types x 4 sites, row = 4*type + site).
// Lane (g=lane>>2, tq=lane&3) owns site g&3; builds its own A frags for all K.
// ---------------------------------------------------------------------------
__global__ void __launch_bounds__(256, 2)
passA_mma(const float* __restrict__ x, const int* __restrict__ signs,
          const float* __restrict__ W1, const float* __restrict__ b1,
          const float* __restrict__ W2, const float* __restrict__ b2,
          const float* __restrict__ W3, const float* __restrict__ b3)
{
    extern __shared__ __align__(256) char sm[];
    float* smf = (float*)sm;
    const int tid  = threadIdx.x;
    const int warp = tid >> 5;
    const int lane = tid & 31;
    const int g    = lane >> 2;      // fragment group (0..7)
    const int tq   = lane & 3;       // thread-in-group
    const int b    = blockIdx.y;

    // ---- stage W2^T hi/lo into pair-permuted smem (validated in R10) ----
    for (int idx = tid; idx < 128 * 128; idx += 256) {
        const int j = idx >> 7, n = idx & 127;      // W2[j][n], k-dim = j
        const float v = W2[idx];
        const __nv_bfloat16 hb = __float2bfloat16(v);
        const __nv_bfloat16 lb = __float2bfloat16(v - __bfloat162float(hb));
        const int pairI = (j >> 1) & 7;
        const int dw    = 2 * (pairI & 3) + (pairI >> 2);
        const uint32_t off = (uint32_t)(n * 256 + (((j >> 4) ^ (n & 7)) << 5)
                                        + dw * 4 + (j & 1) * 2);
        *(__nv_bfloat16*)(sm + OFF_BHI + off) = hb;
        *(__nv_bfloat16*)(sm + OFF_BLO + off) = lb;
    }
    if (tid < 128) {
        const float wa = W1[tid] + W1[256 + tid] + W1[384 + tid];
        const float wb = W1[128 + tid];
        ((float4*)(sm + OFF_W1C))[tid] = make_float4(wa, wb, b1[tid], wa - 4.0f * wb);
        smf[(OFF_B2S >> 2) + tid] = b2[tid];
        smf[(OFF_W3S >> 2) + tid] = W3[tid];
    }
    __syncthreads();

    const float b3v = b3[0];
    const float* xb = x + b * NS;
    const int* sgb  = signs + b * NS;
    const float4* W1c = (const float4*)(sm + OFF_W1C);

    // per-thread stat partials (leaders only nonzero)
    float aSh = 0.f, aSh2 = 0.f, aH2s = 0.f, aHd2s = 0.f, aHH2s = 0.f;
    float aHd[4] = {0,0,0,0}, aHHd[4] = {0,0,0,0};

    const uint32_t bcom = (uint32_t)(256 * g + 8 * tq);
    const int gmask = g & 7;

    for (int it = 0; it < 8; ++it) {
        const int sb = (((blockIdx.x * 8 + warp) * 8) + it) * 4;

        // ---- site aux for THIS lane's site sI = g&3 ----
        float xc, lap, alphaL, bet1L, bet2L, sc; int dL;
        {
            const int s  = sb + (g & 3);
            const int i  = s >> 6, j = s & 63;
            const int iM = (i + 63) & 63, iP = (i + 1) & 63;
            const int jM = (j + 63) & 63, jP = (j + 1) & 63;
            xc  = xb[s];
            lap = xb[(iM << 6) | j] + xb[(iP << 6) | j]
                + xb[(i << 6) | jM] + xb[(i << 6) | jP] - 4.0f * xc;
            dL     = ((i & 1) << 1) | (j & 1);
            alphaL = (float)(2 * sgb[dL * BN + s] - 1);
            bet1L  = (float)(2 * sgb[(dL ^ 1) * BN + ((i << 6) | jM)]
                           + 2 * sgb[(dL ^ 1) * BN + ((i << 6) | jP)] - 2);
            bet2L  = (float)(2 * sgb[(dL ^ 2) * BN + ((iM << 6) | j)]
                           + 2 * sgb[(dL ^ 2) * BN + ((iP << 6) | j)] - 2);
            sc = bet1L * bet1L + bet2L * bet2L;
        }

        // ---- build A fragments in registers ----
        // rows g (tl: type0 if g<4 else type1), g+8 (th: type2 if g<4 else type3)
        uint32_t Ah[8][4], Al[8][4];
        #pragma unroll
        for (int K = 0; K < 8; ++K) {
            float tl[2][2], th[2][2];    // [kpair p][elem e]
            #pragma unroll
            for (int p = 0; p < 2; ++p) {
                #pragma unroll
                for (int e = 0; e < 2; ++e) {
                    const int j = 16 * K + 2 * tq + 8 * p + e;
                    const float4 wc = W1c[j];   // (wa, wb, b1, wd)
                    const float p1 = fmaf(xc, wc.x, fmaf(lap, wc.y, wc.z));
                    float a1v, gp, gpp;
                    gelu3f(p1, a1v, gp, gpp);
                    if (g < 4) {
                        tl[p][e] = a1v;            // type 0
                        th[p][e] = gp * wc.y;      // type 2
                    } else {
                        tl[p][e] = gp * wc.w;      // type 1
                        th[p][e] = gpp * fmaf(sc, wc.y * wc.y, wc.w * wc.w); // type 3
                    }
                }
            }
            Ah[K][0] = cvt2(tl[0][1], tl[0][0]);
            Ah[K][1] = cvt2(th[0][1], th[0][0]);
            Ah[K][2] = cvt2(tl[1][1], tl[1][0]);
            Ah[K][3] = cvt2(th[1][1], th[1][0]);
            Al[K][0] = lo2(Ah[K][0], tl[0][0], tl[0][1]);
            Al[K][1] = lo2(Ah[K][1], th[0][0], th[0][1]);
            Al[K][2] = lo2(Ah[K][2], tl[1][0], tl[1][1]);
            Al[K][3] = lo2(Ah[K][3], th[1][0], th[1][1]);
        }

        // ---- MMA + fused epilogue over 16 n-tiles ----
        float hA = 0.f, S1a = 0.f, S2a = 0.f, S1b = 0.f, S2b = 0.f;
        #pragma unroll 2
        for (int n = 0; n < 16; ++n) {
            float accH[4] = {0, 0, 0, 0}, accL[4] = {0, 0, 0, 0};
            const uint32_t bn = bcom + 2048u * n;
            #pragma unroll
            for (int K = 0; K < 8; ++K) {
                const uint32_t sw = bn + (uint32_t)((K ^ gmask) << 5);
                const uint2 Bh = *(const uint2*)(sm + OFF_BHI + sw);
                mma16816(accH, Ah[K][0], Ah[K][1], Ah[K][2], Ah[K][3], Bh.x, Bh.y);
                mma16816(accL, Al[K][0], Al[K][1], Al[K][2], Al[K][3], Bh.x, Bh.y);
                const uint2 Bl = *(const uint2*)(sm + OFF_BLO + sw);
                mma16816(accL, Ah[K][0], Ah[K][1], Ah[K][2], Ah[K][3], Bl.x, Bl.y);
            }
            float a4[4];
            #pragma unroll
            for (int c = 0; c < 4; ++c) a4[c] = accH[c] + accL[c];

            // epilogue for this n-tile: cols k0, k0+1
            const int k0 = 8 * n + 2 * tq;
            const float2 b2p = *(const float2*)(smf + (OFF_B2S >> 2) + k0);
            const float2 w3p = *(const float2*)(smf + (OFF_W3S >> 2) + k0);
            float a20, gp0, gpp0, a21, gp1, gpp1;
            gelu3f(a4[0] + b2p.x, a20, gp0, gpp0);
            gelu3f(a4[1] + b2p.y, a21, gp1, gpp1);
            hA += a20 * w3p.x + a21 * w3p.y;
            float gw0 = gp0 * w3p.x, gg0 = gpp0 * w3p.x;
            float gw1 = gp1 * w3p.y, gg1 = gpp1 * w3p.y;
            gw0 = __shfl_sync(0xffffffffu, gw0, lane & 15);
            gg0 = __shfl_sync(0xffffffffu, gg0, lane & 15);
            gw1 = __shfl_sync(0xffffffffu, gw1, lane & 15);
            gg1 = __shfl_sync(0xffffffffu, gg1, lane & 15);
            S1a = fmaf(a4[0], gw0, fmaf(a4[1], gw1, S1a));
            S2a = fmaf(a4[0] * a4[0], gg0, fmaf(a4[1] * a4[1], gg1, S2a));
            S1b = fmaf(a4[2], gw0, fmaf(a4[3], gw1, S1b));
            S2b = fmaf(a4[2] * a4[2], gg0, fmaf(a4[3] * a4[3], gg1, S2b));
        }

        // reduce over tq (4 lanes per row)
        #pragma unroll
        for (int o = 1; o <= 2; o <<= 1) {
            hA  += __shfl_xor_sync(0xffffffffu, hA,  o);
            S1a += __shfl_xor_sync(0xffffffffu, S1a, o);
            S2a += __shfl_xor_sync(0xffffffffu, S2a, o);
            S1b += __shfl_xor_sync(0xffffffffu, S1b, o);
            S2b += __shfl_xor_sync(0xffffffffu, S2b, o);
        }
        // cross-half gathers (valid for lanes 0-15)
        const float Pd = __shfl_sync(0xffffffffu, S1a, lane | 16);
        const float PP = __shfl_sync(0xffffffffu, S2a, lane | 16);
        const float UU = __shfl_sync(0xffffffffu, S1b, lane | 16);

        if ((lane & 0x13) == 0) {    // lanes 0,4,8,12 : site = g, aux is local
            const int s = sb + g;
            const float h  = hA + b3v;
            const float Qd = S1b, QQ = S2b;
            g_h [b * NS + s] = h;
            g_da[b * NS + s] = Pd + 4.0f * Qd;
            g_db[b * NS + s] = Qd;
            aSh  += h;
            aSh2 += h * h;
            #pragma unroll
            for (int cc = 0; cc < 4; ++cc) {
                float hd;
                if      (cc == dL)       hd = alphaL * Pd;
                else if (cc == (dL ^ 1)) hd = bet1L  * Qd;
                else if (cc == (dL ^ 2)) hd = bet2L  * Qd;
                else                     hd = 0.0f;
                aHd [cc] += hd;
                aHHd[cc] += h * hd;
            }
            const float h2t = PP + sc * QQ + UU;
            aH2s  += h2t;
            aHd2s += fmaf(sc, Qd * Qd, Pd * Pd);
            aHH2s += h * h2t;
        }
    }

    // warp-level reduction of the 13 partials (non-leader lanes hold zeros)
    float pr[NPART];
    pr[0] = aSh; pr[1] = aSh2;
    #pragma unroll
    for (int c = 0; c < 4; ++c) { pr[2 + c] = aHd[c]; pr[6 + c] = aHHd[c]; }
    pr[10] = aH2s; pr[11] = aHd2s; pr[12] = aHH2s;
    #pragma unroll
    for (int k = 0; k < NPART; ++k) {
        #pragma unroll
        for (int off = 16; off >= 1; off >>= 1)
            pr[k] += __shfl_xor_sync(0xffffffffu, pr[k], off);
    }
    if (lane == 0) {
        #pragma unroll
        for (int k = 0; k < NPART; ++k)
            smf[(OFF_WPART >> 2) + warp * NPART + k] = pr[k];
    }
    __syncthreads();
    if (tid < NPART) {
        float sum = 0.0f;
        #pragma unroll
        for (int w = 0; w < 8; ++w) sum += smf[(OFF_WPART >> 2) + w * NPART + tid];
        g_part[b][blockIdx.x][tid] = sum;
    }
}

// ---------------------------------------------------------------------------
// Pass B: per-batch stats + agg backward (c0,c1) + second-order forward.
// ---------------------------------------------------------------------------
__global__ void passB_kernel(const float* __restrict__ aW1, const float* __restrict__ ab1,
                             const float* __restrict__ aW2, float* __restrict__ out)
{
    __shared__ double S[NPART];
    __shared__ double red0[64], red1[64], red2[64];

    const int b = blockIdx.x, t = threadIdx.x;
    if (t < NPART) {
        double s = 0.0;
        for (int k = 0; k < CPB; ++k) s += (double)g_part[b][k][t];
        S[t] = s;
    }
    __syncthreads();

    const double N = 4096.0, N1 = 4095.0;
    const double m = S[0] / N;
    const double q = S[1] / N;
    const double v = (S[1] - N * m * m) / N1;

    const double a0 = (double)aW1[t], a1 = (double)aW1[64 + t], a2 = (double)aW1[128 + t];
    const double u  = m * a0 + v * a1 + q * a2 + (double)ab1[t];
    const double Phi = normcdf(u);
    const double ph  = 0.39894228040143267794 * exp(-0.5 * u * u);
    const double gp  = Phi + u * ph;
    const double gpp = (2.0 - u * u) * ph;
    const double w2  = (double)aW2[t];

    red0[t] = a0 * gp * w2;
    red1[t] = a1 * gp * w2;
    red2[t] = a2 * gp * w2;
    __syncthreads();
    if (t == 0) {
        double dm = 0, dv = 0, dq = 0;
        for (int i = 0; i < 64; ++i) { dm += red0[i]; dv += red1[i]; dq += red2[i]; }
        g_c01[2 * b]     = (float)(dm / N - 2.0 * dv * m / N1);
        g_c01[2 * b + 1] = (float)(2.0 * dv / N1 + 2.0 * dq / N);
    }
    __syncthreads();

    double quad = 0.0, Smd2 = 0.0;
    #pragma unroll
    for (int c = 0; c < 4; ++c) {
        const double md = S[2 + c] / N;
        const double qd = 2.0 * S[6 + c] / N;
        const double vd = 2.0 * (S[6 + c] - N * m * md) / N1;
        const double ud = md * a0 + vd * a1 + qd * a2;
        quad += gpp * ud * ud;
        Smd2 += md * md;
    }
    const double Smdd = S[10] / N;
    const double Sqdd = 2.0 * (S[11] + S[12]) / N;
    const double Svdd = 2.0 * (S[11] - N * Smd2 + S[12] - m * S[10]) / N1;
    const double Sudd = Smdd * a0 + Svdd * a1 + Sqdd * a2;

    red0[t] = w2 * (quad + gp * Sudd);
    __syncthreads();
    if (t == 0) {
        double L = 0.0;
        for (int i = 0; i < 64; ++i) L += red0[i];
        out[b * 4097 + 4096] = (float)L;
    }
}

// ---------------------------------------------------------------------------
// Pass C: grad = g*da + Stencil(g*db), g = c0 + c1*h.
// ---------------------------------------------------------------------------
__global__ void passC_kernel(float* __restrict__ out)
{
    const int b = blockIdx.y;
    const int s = blockIdx.x * 256 + threadIdx.x;
    const int i = s >> 6, j = s & 63;
    const int iM = (i + 63) & 63, iP = (i + 1) & 63;
    const int jM = (j + 63) & 63, jP = (j + 1) & 63;

    const float c0 = g_c01[2 * b], c1 = g_c01[2 * b + 1];
    const float* h  = g_h  + b * NS;
    const float* db = g_db + b * NS;

    const int nU = (iM << 6) | j, nD = (iP << 6) | j;
    const int nL = (i << 6) | jM, nR = (i << 6) | jP;

    const float gs = fmaf(c1, h[s], c0);
    const float st = fmaf(c1, h[nU], c0) * db[nU]
                   + fmaf(c1, h[nD], c0) * db[nD]
                   + fmaf(c1, h[nL], c0) * db[nL]
                   + fmaf(c1, h[nR], c0) * db[nR]
                   - 4.0f * gs * db[s];
    out[b * 4097 + s] = fmaf(gs, g_da[b * NS + s], st);
}

// ---------------------------------------------------------------------------
extern "C" void kernel_launch(void* const* d_in, const int* in_sizes, int n_in,
                              void* d_out, int out_size)
{
    (void)in_sizes; (void)n_in; (void)out_size;
    const float* x     = (const float*)d_in[0];
    const int*   signs = (const int*)  d_in[1];
    const float* W1    = (const float*)d_in[2];
    const float* b1    = (const float*)d_in[3];
    const float* W2    = (const float*)d_in[4];
    const float* b2    = (const float*)d_in[5];
    const float* W3    = (const float*)d_in[6];
    const float* b3    = (const float*)d_in[7];
    const float* aW1   = (const float*)d_in[8];
    const float* ab1   = (const float*)d_in[9];
    const float* aW2   = (const float*)d_in[10];
    float* out = (float*)d_out;

    cudaFuncSetAttribute(passA_mma, cudaFuncAttributeMaxDynamicSharedMemorySize, SMEMSZ);

    passA_mma<<<dim3(CPB, BATCH), 256, SMEMSZ>>>(x, signs, W1, b1, W2, b2, W3, b3);
    passB_kernel<<<BATCH, 64>>>(aW1, ab1, aW2, out);
    passC_kernel<<<dim3(16, BATCH), 256>>>(out);
}

// round 13
// speedup vs baseline: 1.1742x; 1.1742x over previous
#include <cuda_runtime.h>
#include <cuda_bf16.h>
#include <math.h>
#include <stdint.h>

#define BATCH 64
#define NS 4096
#define CPB 16           // CTAs per batch
#define NPART 13
#define BN (BATCH*NS)

// scratch (device globals; no allocations allowed)
__device__ float g_h [BN];
__device__ float g_da[BN];
__device__ float g_db[BN];
__device__ float g_part[BATCH][CPB][NPART];
__device__ float g_c01[BATCH*2];

// ---------------- smem layout (bytes) ----------------
#define OFF_BHI   0        // W2^T hi: 128 n-rows x 256B, pair-permuted k (32KB)
#define OFF_BLO   32768    // (32KB)
#define OFF_W1C   65536    // 128 x float4 (wa, wb, b1, wd)  (2KB)
#define OFF_B2S   67584
#define OFF_W3S   68096
#define OFF_WPART 68608    // 8 warps x 13 floats
#define SMEMSZ    69120

__device__ __forceinline__ void gelu3f(float x, float& v, float& d1, float& d2) {
    float Phi = normcdff(x);
    float ph  = 0.3989422804014326779f * __expf(-0.5f * x * x);
    v  = x * Phi;
    d1 = fmaf(x, ph, Phi);
    d2 = (2.0f - x * x) * ph;
}
__device__ __forceinline__ uint32_t cvt2(float hi, float lo) {
    uint32_t r;
    asm("cvt.rn.bf16x2.f32 %0, %1, %2;" : "=r"(r) : "f"(hi), "f"(lo));
    return r;
}
// residual pack: h holds bf16x2(hi=e1, lo=e0); return bf16x2 of residuals
__device__ __forceinline__ uint32_t lo2(uint32_t h, float e0, float e1) {
    const float f0 = __uint_as_float(h << 16);
    const float f1 = __uint_as_float(h & 0xffff0000u);
    return cvt2(e1 - f1, e0 - f0);
}
__device__ __forceinline__ void mma16816(float* d, uint32_t a0, uint32_t a1,
                                         uint32_t a2, uint32_t a3,
                                         uint32_t b0, uint32_t b1) {
    asm volatile(
        "mma.sync.aligned.m16n8k16.row.col.f32.bf16.bf16.f32 "
        "{%0,%1,%2,%3}, {%4,%5,%6,%7}, {%8,%9}, {%0,%1,%2,%3};"
        : "+f"(d[0]), "+f"(d[1]), "+f"(d[2]), "+f"(d[3])
        : "r"(a0), "r"(a1), "r"(a2), "r"(a3), "r"(b0), "r"(b1));
}

// ---------------------------------------------------------------------------
// Pass A: grid (CPB, BATCH), 256 thr, 8 warps. Warp-iter: 4 sites
// (16 rows = 4 types x 4 sites; row = 4*type + site... fragment rows: lane
// group g holds rows g / g+8; row g <-> type (g<4 ? 0/2 : 1/3), site g&3).
// K-outer, n-inner, acc[16][4] for full MMA ILP. Gelu dedup: lanes<16 compute
// p=0 columns, lanes>=16 p=1 columns; two shfl.xor(16) exchange the halves.
// ---------------------------------------------------------------------------
__global__ void __launch_bounds__(256, 2)
passA_mma(const float* __restrict__ x, const int* __restrict__ signs,
          const float* __restrict__ W1, const float* __restrict__ b1,
          const float* __restrict__ W2, const float* __restrict__ b2,
          const float* __restrict__ W3, const float* __restrict__ b3)
{
    extern __shared__ __align__(256) char sm[];
    float* smf = (float*)sm;
    const int tid  = threadIdx.x;
    const int warp = tid >> 5;
    const int lane = tid & 31;
    const int g    = lane >> 2;      // fragment group (0..7)
    const int tq   = lane & 3;       // thread-in-group
    const int b    = blockIdx.y;

    // ---- stage W2^T hi/lo into pair-permuted smem (validated R10/R11) ----
    for (int idx = tid; idx < 128 * 128; idx += 256) {
        const int j = idx >> 7, n = idx & 127;      // W2[j][n], k-dim = j
        const float v = W2[idx];
        const __nv_bfloat16 hb = __float2bfloat16(v);
        const __nv_bfloat16 lb = __float2bfloat16(v - __bfloat162float(hb));
        const int pairI = (j >> 1) & 7;
        const int dw    = 2 * (pairI & 3) + (pairI >> 2);
        const uint32_t off = (uint32_t)(n * 256 + (((j >> 4) ^ (n & 7)) << 5)
                                        + dw * 4 + (j & 1) * 2);
        *(__nv_bfloat16*)(sm + OFF_BHI + off) = hb;
        *(__nv_bfloat16*)(sm + OFF_BLO + off) = lb;
    }
    if (tid < 128) {
        const float wa = W1[tid] + W1[256 + tid] + W1[384 + tid];
        const float wb = W1[128 + tid];
        ((float4*)(sm + OFF_W1C))[tid] = make_float4(wa, wb, b1[tid], wa - 4.0f * wb);
        smf[(OFF_B2S >> 2) + tid] = b2[tid];
        smf[(OFF_W3S >> 2) + tid] = W3[tid];
    }
    __syncthreads();

    const float b3v = b3[0];
    const float* xb = x + b * NS;
    const int* sgb  = signs + b * NS;
    const float4* W1c = (const float4*)(sm + OFF_W1C);

    // per-thread stat partials (leaders only nonzero)
    float aSh = 0.f, aSh2 = 0.f, aH2s = 0.f, aHd2s = 0.f, aHH2s = 0.f;
    float aHd[4] = {0,0,0,0}, aHHd[4] = {0,0,0,0};

    const uint32_t bcom = (uint32_t)(256 * g + 8 * tq);
    const int gmask = g & 7;
    const bool lowhalf = (lane < 16);
    const int coff = 2 * tq + (lowhalf ? 0 : 8);   // this lane's computed cols

    for (int it = 0; it < 8; ++it) {
        const int sb = (((blockIdx.x * 8 + warp) * 8) + it) * 4;

        // ---- site aux for THIS lane's site sI = g&3 ----
        float xc, lap, alphaL, bet1L, bet2L, sc; int dL;
        {
            const int s  = sb + (g & 3);
            const int i  = s >> 6, j = s & 63;
            const int iM = (i + 63) & 63, iP = (i + 1) & 63;
            const int jM = (j + 63) & 63, jP = (j + 1) & 63;
            xc  = xb[s];
            lap = xb[(iM << 6) | j] + xb[(iP << 6) | j]
                + xb[(i << 6) | jM] + xb[(i << 6) | jP] - 4.0f * xc;
            dL     = ((i & 1) << 1) | (j & 1);
            alphaL = (float)(2 * sgb[dL * BN + s] - 1);
            bet1L  = (float)(2 * sgb[(dL ^ 1) * BN + ((i << 6) | jM)]
                           + 2 * sgb[(dL ^ 1) * BN + ((i << 6) | jP)] - 2);
            bet2L  = (float)(2 * sgb[(dL ^ 2) * BN + ((iM << 6) | j)]
                           + 2 * sgb[(dL ^ 2) * BN + ((iP << 6) | j)] - 2);
            sc = bet1L * bet1L + bet2L * bet2L;
        }

        // ---- K-outer MMA with full acc ILP ----
        float acc[16][4];
        #pragma unroll
        for (int n = 0; n < 16; ++n)
            #pragma unroll
            for (int c = 0; c < 4; ++c) acc[n][c] = 0.0f;

        #pragma unroll
        for (int K = 0; K < 8; ++K) {
            // -- build this K's A fragments (gelu dedup via partner exchange) --
            // lane computes 2 cols (cbase, cbase+1); all 4 type-values each.
            float t0o[2], t1o[2], t2o[2], t3o[2];
            const int cbase = 16 * K + coff;
            #pragma unroll
            for (int e = 0; e < 2; ++e) {
                const float4 wc = W1c[cbase + e];   // (wa, wb, b1, wd)
                const float p1 = fmaf(xc, wc.x, fmaf(lap, wc.y, wc.z));
                float a1v, gp, gpp;
                gelu3f(p1, a1v, gp, gpp);
                t0o[e] = a1v;                                   // type 0
                t1o[e] = gp * wc.w;                             // type 1
                t2o[e] = gp * wc.y;                             // type 2
                t3o[e] = gpp * fmaf(sc, wc.y * wc.y, wc.w * wc.w); // type 3
            }
            // exchange: low half keeps (t0,t2), sends (t1,t3); high keeps (t1,t3)
            float a0v[2], a1w[2], a2v[2], a3v[2];
            #pragma unroll
            for (int e = 0; e < 2; ++e) {
                const float sendA = lowhalf ? t1o[e] : t0o[e];
                const float sendB = lowhalf ? t3o[e] : t2o[e];
                const float recvA = __shfl_xor_sync(0xffffffffu, sendA, 16);
                const float recvB = __shfl_xor_sync(0xffffffffu, sendB, 16);
                a0v[e] = lowhalf ? t0o[e] : recvA;   // row g,   k-pair p=0
                a1w[e] = lowhalf ? t2o[e] : recvB;   // row g+8, p=0
                a2v[e] = lowhalf ? recvA : t1o[e];   // row g,   p=1
                a3v[e] = lowhalf ? recvB : t3o[e];   // row g+8, p=1
            }
            const uint32_t Ah0 = cvt2(a0v[1], a0v[0]);
            const uint32_t Ah1 = cvt2(a1w[1], a1w[0]);
            const uint32_t Ah2 = cvt2(a2v[1], a2v[0]);
            const uint32_t Ah3 = cvt2(a3v[1], a3v[0]);
            const uint32_t Al0 = lo2(Ah0, a0v[0], a0v[1]);
            const uint32_t Al1 = lo2(Ah1, a1w[0], a1w[1]);
            const uint32_t Al2 = lo2(Ah2, a2v[0], a2v[1]);
            const uint32_t Al3 = lo2(Ah3, a3v[0], a3v[1]);

            // -- n-sweep: 16 independent acc chains --
            const uint32_t swK = bcom + (uint32_t)((K ^ gmask) << 5);
            #pragma unroll
            for (int n = 0; n < 16; ++n) {
                const uint32_t sw = swK + 2048u * n;
                const uint2 Bh = *(const uint2*)(sm + OFF_BHI + sw);
                mma16816(acc[n], Ah0, Ah1, Ah2, Ah3, Bh.x, Bh.y);
                mma16816(acc[n], Al0, Al1, Al2, Al3, Bh.x, Bh.y);
                const uint2 Bl = *(const uint2*)(sm + OFF_BLO + sw);
                mma16816(acc[n], Ah0, Ah1, Ah2, Ah3, Bl.x, Bl.y);
            }
        }

        // ---- epilogue (same structure as validated R11) ----
        float hA = 0.f, S1a = 0.f, S2a = 0.f, S1b = 0.f, S2b = 0.f;
        #pragma unroll
        for (int n = 0; n < 16; ++n) {
            const int k0 = 8 * n + 2 * tq;
            const float2 b2p = *(const float2*)(smf + (OFF_B2S >> 2) + k0);
            const float2 w3p = *(const float2*)(smf + (OFF_W3S >> 2) + k0);
            float a20, gp0, gpp0, a21, gp1, gpp1;
            gelu3f(acc[n][0] + b2p.x, a20, gp0, gpp0);
            gelu3f(acc[n][1] + b2p.y, a21, gp1, gpp1);
            hA += a20 * w3p.x + a21 * w3p.y;
            float gw0 = gp0 * w3p.x, gg0 = gpp0 * w3p.x;
            float gw1 = gp1 * w3p.y, gg1 = gpp1 * w3p.y;
            gw0 = __shfl_sync(0xffffffffu, gw0, lane & 15);
            gg0 = __shfl_sync(0xffffffffu, gg0, lane & 15);
            gw1 = __shfl_sync(0xffffffffu, gw1, lane & 15);
            gg1 = __shfl_sync(0xffffffffu, gg1, lane & 15);
            S1a = fmaf(acc[n][0], gw0, fmaf(acc[n][1], gw1, S1a));
            S2a = fmaf(acc[n][0] * acc[n][0], gg0, fmaf(acc[n][1] * acc[n][1], gg1, S2a));
            S1b = fmaf(acc[n][2], gw0, fmaf(acc[n][3], gw1, S1b));
            S2b = fmaf(acc[n][2] * acc[n][2], gg0, fmaf(acc[n][3] * acc[n][3], gg1, S2b));
        }

        // reduce over tq (4 lanes per row)
        #pragma unroll
        for (int o = 1; o <= 2; o <<= 1) {
            hA  += __shfl_xor_sync(0xffffffffu, hA,  o);
            S1a += __shfl_xor_sync(0xffffffffu, S1a, o);
            S2a += __shfl_xor_sync(0xffffffffu, S2a, o);
            S1b += __shfl_xor_sync(0xffffffffu, S1b, o);
            S2b += __shfl_xor_sync(0xffffffffu, S2b, o);
        }
        // cross-half gathers (valid for lanes 0-15)
        const float Pd = __shfl_sync(0xffffffffu, S1a, lane | 16);
        const float PP = __shfl_sync(0xffffffffu, S2a, lane | 16);
        const float UU = __shfl_sync(0xffffffffu, S1b, lane | 16);

        if ((lane & 0x13) == 0) {    // lanes 0,4,8,12 : site = g, aux is local
            const int s = sb + g;
            const float h  = hA + b3v;
            const float Qd = S1b, QQ = S2b;
            g_h [b * NS + s] = h;
            g_da[b * NS + s] = Pd + 4.0f * Qd;
            g_db[b * NS + s] = Qd;
            aSh  += h;
            aSh2 += h * h;
            #pragma unroll
            for (int cc = 0; cc < 4; ++cc) {
                float hd;
                if      (cc == dL)       hd = alphaL * Pd;
                else if (cc == (dL ^ 1)) hd = bet1L  * Qd;
                else if (cc == (dL ^ 2)) hd = bet2L  * Qd;
                else                     hd = 0.0f;
                aHd [cc] += hd;
                aHHd[cc] += h * hd;
            }
            const float h2t = PP + sc * QQ + UU;
            aH2s  += h2t;
            aHd2s += fmaf(sc, Qd * Qd, Pd * Pd);
            aHH2s += h * h2t;
        }
    }

    // warp-level reduction of the 13 partials (non-leader lanes hold zeros)
    float pr[NPART];
    pr[0] = aSh; pr[1] = aSh2;
    #pragma unroll
    for (int c = 0; c < 4; ++c) { pr[2 + c] = aHd[c]; pr[6 + c] = aHHd[c]; }
    pr[10] = aH2s; pr[11] = aHd2s; pr[12] = aHH2s;
    #pragma unroll
    for (int k = 0; k < NPART; ++k) {
        #pragma unroll
        for (int off = 16; off >= 1; off >>= 1)
            pr[k] += __shfl_xor_sync(0xffffffffu, pr[k], off);
    }
    if (lane == 0) {
        #pragma unroll
        for (int k = 0; k < NPART; ++k)
            smf[(OFF_WPART >> 2) + warp * NPART + k] = pr[k];
    }
    __syncthreads();
    if (tid < NPART) {
        float sum = 0.0f;
        #pragma unroll
        for (int w = 0; w < 8; ++w) sum += smf[(OFF_WPART >> 2) + w * NPART + tid];
        g_part[b][blockIdx.x][tid] = sum;
    }
}

// ---------------------------------------------------------------------------
// Pass B: per-batch stats + agg backward (c0,c1) + second-order forward.
// ---------------------------------------------------------------------------
__global__ void passB_kernel(const float* __restrict__ aW1, const float* __restrict__ ab1,
                             const float* __restrict__ aW2, float* __restrict__ out)
{
    __shared__ double S[NPART];
    __shared__ double red0[64], red1[64], red2[64];

    const int b = blockIdx.x, t = threadIdx.x;
    if (t < NPART) {
        double s = 0.0;
        for (int k = 0; k < CPB; ++k) s += (double)g_part[b][k][t];
        S[t] = s;
    }
    __syncthreads();

    const double N = 4096.0, N1 = 4095.0;
    const double m = S[0] / N;
    const double q = S[1] / N;
    const double v = (S[1] - N * m * m) / N1;

    const double a0 = (double)aW1[t], a1 = (double)aW1[64 + t], a2 = (double)aW1[128 + t];
    const double u  = m * a0 + v * a1 + q * a2 + (double)ab1[t];
    const double Phi = normcdf(u);
    const double ph  = 0.39894228040143267794 * exp(-0.5 * u * u);
    const double gp  = Phi + u * ph;
    const double gpp = (2.0 - u * u) * ph;
    const double w2  = (double)aW2[t];

    red0[t] = a0 * gp * w2;
    red1[t] = a1 * gp * w2;
    red2[t] = a2 * gp * w2;
    __syncthreads();
    if (t == 0) {
        double dm = 0, dv = 0, dq = 0;
        for (int i = 0; i < 64; ++i) { dm += red0[i]; dv += red1[i]; dq += red2[i]; }
        g_c01[2 * b]     = (float)(dm / N - 2.0 * dv * m / N1);
        g_c01[2 * b + 1] = (float)(2.0 * dv / N1 + 2.0 * dq / N);
    }
    __syncthreads();

    double quad = 0.0, Smd2 = 0.0;
    #pragma unroll
    for (int c = 0; c < 4; ++c) {
        const double md = S[2 + c] / N;
        const double qd = 2.0 * S[6 + c] / N;
        const double vd = 2.0 * (S[6 + c] - N * m * md) / N1;
        const double ud = md * a0 + vd * a1 + qd * a2;
        quad += gpp * ud * ud;
        Smd2 += md * md;
    }
    const double Smdd = S[10] / N;
    const double Sqdd = 2.0 * (S[11] + S[12]) / N;
    const double Svdd = 2.0 * (S[11] - N * Smd2 + S[12] - m * S[10]) / N1;
    const double Sudd = Smdd * a0 + Svdd * a1 + Sqdd * a2;

    red0[t] = w2 * (quad + gp * Sudd);
    __syncthreads();
    if (t == 0) {
        double L = 0.0;
        for (int i = 0; i < 64; ++i) L += red0[i];
        out[b * 4097 + 4096] = (float)L;
    }
}

// ---------------------------------------------------------------------------
// Pass C: grad = g*da + Stencil(g*db), g = c0 + c1*h.
// ---------------------------------------------------------------------------
__global__ void passC_kernel(float* __restrict__ out)
{
    const int b = blockIdx.y;
    const int s = blockIdx.x * 256 + threadIdx.x;
    const int i = s >> 6, j = s & 63;
    const int iM = (i + 63) & 63, iP = (i + 1) & 63;
    const int jM = (j + 63) & 63, jP = (j + 1) & 63;

    const float c0 = g_c01[2 * b], c1 = g_c01[2 * b + 1];
    const float* h  = g_h  + b * NS;
    const float* db = g_db + b * NS;

    const int nU = (iM << 6) | j, nD = (iP << 6) | j;
    const int nL = (i << 6) | jM, nR = (i << 6) | jP;

    const float gs = fmaf(c1, h[s], c0);
    const float st = fmaf(c1, h[nU], c0) * db[nU]
                   + fmaf(c1, h[nD], c0) * db[nD]
                   + fmaf(c1, h[nL], c0) * db[nL]
                   + fmaf(c1, h[nR], c0) * db[nR]
                   - 4.0f * gs * db[s];
    out[b * 4097 + s] = fmaf(gs, g_da[b * NS + s], st);
}

// ---------------------------------------------------------------------------
extern "C" void kernel_launch(void* const* d_in, const int* in_sizes, int n_in,
                              void* d_out, int out_size)
{
    (void)in_sizes; (void)n_in; (void)out_size;
    const float* x     = (const float*)d_in[0];
    const int*   signs = (const int*)  d_in[1];
    const float* W1    = (const float*)d_in[2];
    const float* b1    = (const float*)d_in[3];
    const float* W2    = (const float*)d_in[4];
    const float* b2    = (const float*)d_in[5];
    const float* W3    = (const float*)d_in[6];
    const float* b3    = (const float*)d_in[7];
    const float* aW1   = (const float*)d_in[8];
    const float* ab1   = (const float*)d_in[9];
    const float* aW2   = (const float*)d_in[10];
    float* out = (float*)d_out;

    cudaFuncSetAttribute(passA_mma, cudaFuncAttributeMaxDynamicSharedMemorySize, SMEMSZ);

    passA_mma<<<dim3(CPB, BATCH), 256, SMEMSZ>>>(x, signs, W1, b1, W2, b2, W3, b3);
    passB_kernel<<<BATCH, 64>>>(aW1, ab1, aW2, out);
    passC_kernel<<<dim3(16, BATCH), 256>>>(out);
}

// round 14
// speedup vs baseline: 1.7481x; 1.4888x over previous
#include <cuda_runtime.h>
#include <cuda_bf16.h>
#include <math.h>
#include <stdint.h>

#define BATCH 64
#define NS 4096
#define CPB 16           // CTAs per batch
#define NPART 13
#define BN (BATCH*NS)

// scratch (device globals; no allocations allowed)
__device__ float g_h [BN];
__device__ float g_da[BN];
__device__ float g_db[BN];
__device__ float g_part[BATCH][CPB][NPART];
__device__ float g_c01[BATCH*2];

// ---------------- smem layout (bytes) ----------------
#define OFF_BHI   0        // W2^T hi: 128 n-rows x 256B, pair-permuted k (32KB)
#define OFF_BLO   32768    // (32KB)
#define OFF_W1C   65536    // 128 x float4 (wa, wb, b1, wd)  (2KB)
#define OFF_B2S   67584
#define OFF_W3S   68096
#define OFF_WPART 68608    // 8 warps x 13 floats
#define SMEMSZ    69120

// fast exact-erf GELU triple via Abramowitz-Stegun 26.2.17 (|eps|<7.5e-8):
// v = x*Phi(x), d1 = Phi + x*phi, d2 = (2 - x^2)*phi
__device__ __forceinline__ void gelu3f(float x, float& v, float& d1, float& d2) {
    const float ax = fabsf(x);
    const float ph = 0.3989422804014327f * __expf(-0.5f * x * x);
    const float t  = __fdividef(1.0f, fmaf(0.2316419f, ax, 1.0f));
    const float poly = t * fmaf(t, fmaf(t, fmaf(t, fmaf(t, 1.330274429f,
                        -1.821255978f), 1.781477937f), -0.356563782f), 0.319381530f);
    const float q   = ph * poly;                 // 1 - Phi(|x|)
    const float Phi = (x >= 0.0f) ? (1.0f - q) : q;
    v  = x * Phi;
    d1 = fmaf(x, ph, Phi);
    d2 = (2.0f - x * x) * ph;
}
__device__ __forceinline__ uint32_t cvt2(float hi, float lo) {
    uint32_t r;
    asm("cvt.rn.bf16x2.f32 %0, %1, %2;" : "=r"(r) : "f"(hi), "f"(lo));
    return r;
}
// residual pack: h holds bf16x2(hi=e1, lo=e0); return bf16x2 of residuals
__device__ __forceinline__ uint32_t lo2(uint32_t h, float e0, float e1) {
    const float f0 = __uint_as_float(h << 16);
    const float f1 = __uint_as_float(h & 0xffff0000u);
    return cvt2(e1 - f1, e0 - f0);
}
__device__ __forceinline__ void mma16816(float* d, uint32_t a0, uint32_t a1,
                                         uint32_t a2, uint32_t a3,
                                         uint32_t b0, uint32_t b1) {
    asm volatile(
        "mma.sync.aligned.m16n8k16.row.col.f32.bf16.bf16.f32 "
        "{%0,%1,%2,%3}, {%4,%5,%6,%7}, {%8,%9}, {%0,%1,%2,%3};"
        : "+f"(d[0]), "+f"(d[1]), "+f"(d[2]), "+f"(d[3])
        : "r"(a0), "r"(a1), "r"(a2), "r"(a3), "r"(b0), "r"(b1));
}

// ---------------------------------------------------------------------------
// Pass A: grid (CPB, BATCH), 256 thr, 8 warps. Warp-iter: 4 sites
// (fragment rows: lane group g holds rows g / g+8; row g <-> type
// (g<4 ? 0/2 : 1/3), site g&3). K-outer, n-inner, acc[16][4] for MMA ILP.
// Gelu dedup: lanes<16 compute p=0 cols, lanes>=16 p=1; shfl.xor(16) exchange.
// ---------------------------------------------------------------------------
__global__ void __launch_bounds__(256, 2)
passA_mma(const float* __restrict__ x, const int* __restrict__ signs,
          const float* __restrict__ W1, const float* __restrict__ b1,
          const float* __restrict__ W2, const float* __restrict__ b2,
          const float* __restrict__ W3, const float* __restrict__ b3)
{
    extern __shared__ __align__(256) char sm[];
    float* smf = (float*)sm;
    const int tid  = threadIdx.x;
    const int warp = tid >> 5;
    const int lane = tid & 31;
    const int g    = lane >> 2;      // fragment group (0..7)
    const int tq   = lane & 3;       // thread-in-group
    const int b    = blockIdx.y;

    // ---- stage W2^T hi/lo into pair-permuted smem (validated R10/R12) ----
    for (int idx = tid; idx < 128 * 128; idx += 256) {
        const int j = idx >> 7, n = idx & 127;      // W2[j][n], k-dim = j
        const float v = W2[idx];
        const __nv_bfloat16 hb = __float2bfloat16(v);
        const __nv_bfloat16 lb = __float2bfloat16(v - __bfloat162float(hb));
        const int pairI = (j >> 1) & 7;
        const int dw    = 2 * (pairI & 3) + (pairI >> 2);
        const uint32_t off = (uint32_t)(n * 256 + (((j >> 4) ^ (n & 7)) << 5)
                                        + dw * 4 + (j & 1) * 2);
        *(__nv_bfloat16*)(sm + OFF_BHI + off) = hb;
        *(__nv_bfloat16*)(sm + OFF_BLO + off) = lb;
    }
    if (tid < 128) {
        const float wa = W1[tid] + W1[256 + tid] + W1[384 + tid];
        const float wb = W1[128 + tid];
        ((float4*)(sm + OFF_W1C))[tid] = make_float4(wa, wb, b1[tid], wa - 4.0f * wb);
        smf[(OFF_B2S >> 2) + tid] = b2[tid];
        smf[(OFF_W3S >> 2) + tid] = W3[tid];
    }
    __syncthreads();

    const float b3v = b3[0];
    const float* xb = x + b * NS;
    const int* sgb  = signs + b * NS;
    const float4* W1c = (const float4*)(sm + OFF_W1C);

    // per-thread stat partials (leaders only nonzero)
    float aSh = 0.f, aSh2 = 0.f, aH2s = 0.f, aHd2s = 0.f, aHH2s = 0.f;
    float aHd[4] = {0,0,0,0}, aHHd[4] = {0,0,0,0};

    const uint32_t bcom = (uint32_t)(256 * g + 8 * tq);
    const int gmask = g & 7;
    const bool lowhalf = (lane < 16);
    const int coff = 2 * tq + (lowhalf ? 0 : 8);   // this lane's computed cols

    for (int it = 0; it < 8; ++it) {
        const int sb = (((blockIdx.x * 8 + warp) * 8) + it) * 4;

        // ---- site aux for THIS lane's site sI = g&3 ----
        float xc, lap, alphaL, bet1L, bet2L, sc; int dL;
        {
            const int s  = sb + (g & 3);
            const int i  = s >> 6, j = s & 63;
            const int iM = (i + 63) & 63, iP = (i + 1) & 63;
            const int jM = (j + 63) & 63, jP = (j + 1) & 63;
            xc  = xb[s];
            lap = xb[(iM << 6) | j] + xb[(iP << 6) | j]
                + xb[(i << 6) | jM] + xb[(i << 6) | jP] - 4.0f * xc;
            dL     = ((i & 1) << 1) | (j & 1);
            alphaL = (float)(2 * sgb[dL * BN + s] - 1);
            bet1L  = (float)(2 * sgb[(dL ^ 1) * BN + ((i << 6) | jM)]
                           + 2 * sgb[(dL ^ 1) * BN + ((i << 6) | jP)] - 2);
            bet2L  = (float)(2 * sgb[(dL ^ 2) * BN + ((iM << 6) | j)]
                           + 2 * sgb[(dL ^ 2) * BN + ((iP << 6) | j)] - 2);
            sc = bet1L * bet1L + bet2L * bet2L;
        }

        // ---- K-outer MMA with full acc ILP ----
        float acc[16][4];
        #pragma unroll
        for (int n = 0; n < 16; ++n)
            #pragma unroll
            for (int c = 0; c < 4; ++c) acc[n][c] = 0.0f;

        #pragma unroll
        for (int K = 0; K < 8; ++K) {
            // -- build this K's A fragments (gelu dedup via partner exchange) --
            float t0o[2], t1o[2], t2o[2], t3o[2];
            const int cbase = 16 * K + coff;
            #pragma unroll
            for (int e = 0; e < 2; ++e) {
                const float4 wc = W1c[cbase + e];   // (wa, wb, b1, wd)
                const float p1 = fmaf(xc, wc.x, fmaf(lap, wc.y, wc.z));
                float a1v, gp, gpp;
                gelu3f(p1, a1v, gp, gpp);
                t0o[e] = a1v;                                   // type 0
                t1o[e] = gp * wc.w;                             // type 1
                t2o[e] = gp * wc.y;                             // type 2
                t3o[e] = gpp * fmaf(sc, wc.y * wc.y, wc.w * wc.w); // type 3
            }
            // exchange: low half keeps (t0,t2), sends (t1,t3); high keeps (t1,t3)
            float a0v[2], a1w[2], a2v[2], a3v[2];
            #pragma unroll
            for (int e = 0; e < 2; ++e) {
                const float sendA = lowhalf ? t1o[e] : t0o[e];
                const float sendB = lowhalf ? t3o[e] : t2o[e];
                const float recvA = __shfl_xor_sync(0xffffffffu, sendA, 16);
                const float recvB = __shfl_xor_sync(0xffffffffu, sendB, 16);
                a0v[e] = lowhalf ? t0o[e] : recvA;   // row g,   k-pair p=0
                a1w[e] = lowhalf ? t2o[e] : recvB;   // row g+8, p=0
                a2v[e] = lowhalf ? recvA : t1o[e];   // row g,   p=1
                a3v[e] = lowhalf ? recvB : t3o[e];   // row g+8, p=1
            }
            const uint32_t Ah0 = cvt2(a0v[1], a0v[0]);
            const uint32_t Ah1 = cvt2(a1w[1], a1w[0]);
            const uint32_t Ah2 = cvt2(a2v[1], a2v[0]);
            const uint32_t Ah3 = cvt2(a3v[1], a3v[0]);
            const uint32_t Al0 = lo2(Ah0, a0v[0], a0v[1]);
            const uint32_t Al1 = lo2(Ah1, a1w[0], a1w[1]);
            const uint32_t Al2 = lo2(Ah2, a2v[0], a2v[1]);
            const uint32_t Al3 = lo2(Ah3, a3v[0], a3v[1]);

            // -- n-sweep: 16 independent acc chains --
            const uint32_t swK = bcom + (uint32_t)((K ^ gmask) << 5);
            #pragma unroll
            for (int n = 0; n < 16; ++n) {
                const uint32_t sw = swK + 2048u * n;
                const uint2 Bh = *(const uint2*)(sm + OFF_BHI + sw);
                mma16816(acc[n], Ah0, Ah1, Ah2, Ah3, Bh.x, Bh.y);
                mma16816(acc[n], Al0, Al1, Al2, Al3, Bh.x, Bh.y);
                const uint2 Bl = *(const uint2*)(sm + OFF_BLO + sw);
                mma16816(acc[n], Ah0, Ah1, Ah2, Ah3, Bl.x, Bl.y);
            }
        }

        // ---- epilogue ----
        float hA = 0.f, S1a = 0.f, S2a = 0.f, S1b = 0.f, S2b = 0.f;
        #pragma unroll
        for (int n = 0; n < 16; ++n) {
            const int k0 = 8 * n + 2 * tq;
            const float2 b2p = *(const float2*)(smf + (OFF_B2S >> 2) + k0);
            const float2 w3p = *(const float2*)(smf + (OFF_W3S >> 2) + k0);
            float a20, gp0, gpp0, a21, gp1, gpp1;
            gelu3f(acc[n][0] + b2p.x, a20, gp0, gpp0);
            gelu3f(acc[n][1] + b2p.y, a21, gp1, gpp1);
            hA += a20 * w3p.x + a21 * w3p.y;
            float gw0 = gp0 * w3p.x, gg0 = gpp0 * w3p.x;
            float gw1 = gp1 * w3p.y, gg1 = gpp1 * w3p.y;
            gw0 = __shfl_sync(0xffffffffu, gw0, lane & 15);
            gg0 = __shfl_sync(0xffffffffu, gg0, lane & 15);
            gw1 = __shfl_sync(0xffffffffu, gw1, lane & 15);
            gg1 = __shfl_sync(0xffffffffu, gg1, lane & 15);
            S1a = fmaf(acc[n][0], gw0, fmaf(acc[n][1], gw1, S1a));
            S2a = fmaf(acc[n][0] * acc[n][0], gg0, fmaf(acc[n][1] * acc[n][1], gg1, S2a));
            S1b = fmaf(acc[n][2], gw0, fmaf(acc[n][3], gw1, S1b));
            S2b = fmaf(acc[n][2] * acc[n][2], gg0, fmaf(acc[n][3] * acc[n][3], gg1, S2b));
        }

        // reduce over tq (4 lanes per row)
        #pragma unroll
        for (int o = 1; o <= 2; o <<= 1) {
            hA  += __shfl_xor_sync(0xffffffffu, hA,  o);
            S1a += __shfl_xor_sync(0xffffffffu, S1a, o);
            S2a += __shfl_xor_sync(0xffffffffu, S2a, o);
            S1b += __shfl_xor_sync(0xffffffffu, S1b, o);
            S2b += __shfl_xor_sync(0xffffffffu, S2b, o);
        }
        // cross-half gathers (valid for lanes 0-15)
        const float Pd = __shfl_sync(0xffffffffu, S1a, lane | 16);
        const float PP = __shfl_sync(0xffffffffu, S2a, lane | 16);
        const float UU = __shfl_sync(0xffffffffu, S1b, lane | 16);

        if ((lane & 0x13) == 0) {    // lanes 0,4,8,12 : site = g, aux is local
            const int s = sb + g;
            const float h  = hA + b3v;
            const float Qd = S1b, QQ = S2b;
            g_h [b * NS + s] = h;
            g_da[b * NS + s] = Pd + 4.0f * Qd;
            g_db[b * NS + s] = Qd;
            aSh  += h;
            aSh2 += h * h;
            #pragma unroll
            for (int cc = 0; cc < 4; ++cc) {
                float hd;
                if      (cc == dL)       hd = alphaL * Pd;
                else if (cc == (dL ^ 1)) hd = bet1L  * Qd;
                else if (cc == (dL ^ 2)) hd = bet2L  * Qd;
                else                     hd = 0.0f;
                aHd [cc] += hd;
                aHHd[cc] += h * hd;
            }
            const float h2t = PP + sc * QQ + UU;
            aH2s  += h2t;
            aHd2s += fmaf(sc, Qd * Qd, Pd * Pd);
            aHH2s += h * h2t;
        }
    }

    // warp-level reduction of the 13 partials (non-leader lanes hold zeros)
    float pr[NPART];
    pr[0] = aSh; pr[1] = aSh2;
    #pragma unroll
    for (int c = 0; c < 4; ++c) { pr[2 + c] = aHd[c]; pr[6 + c] = aHHd[c]; }
    pr[10] = aH2s; pr[11] = aHd2s; pr[12] = aHH2s;
    #pragma unroll
    for (int k = 0; k < NPART; ++k) {
        #pragma unroll
        for (int off = 16; off >= 1; off >>= 1)
            pr[k] += __shfl_xor_sync(0xffffffffu, pr[k], off);
    }
    if (lane == 0) {
        #pragma unroll
        for (int k = 0; k < NPART; ++k)
            smf[(OFF_WPART >> 2) + warp * NPART + k] = pr[k];
    }
    __syncthreads();
    if (tid < NPART) {
        float sum = 0.0f;
        #pragma unroll
        for (int w = 0; w < 8; ++w) sum += smf[(OFF_WPART >> 2) + w * NPART + tid];
        g_part[b][blockIdx.x][tid] = sum;
    }
}

// ---------------------------------------------------------------------------
// Pass B: per-batch stats + agg backward (c0,c1) + second-order forward.
// (double precision, exact normcdf — cost negligible at this size)
// ---------------------------------------------------------------------------
__global__ void passB_kernel(const float* __restrict__ aW1, const float* __restrict__ ab1,
                             const float* __restrict__ aW2, float* __restrict__ out)
{
    __shared__ double S[NPART];
    __shared__ double red0[64], red1[64], red2[64];

    const int b = blockIdx.x, t = threadIdx.x;
    if (t < NPART) {
        double s = 0.0;
        for (int k = 0; k < CPB; ++k) s += (double)g_part[b][k][t];
        S[t] = s;
    }
    __syncthreads();

    const double N = 4096.0, N1 = 4095.0;
    const double m = S[0] / N;
    const double q = S[1] / N;
    const double v = (S[1] - N * m * m) / N1;

    const double a0 = (double)aW1[t], a1 = (double)aW1[64 + t], a2 = (double)aW1[128 + t];
    const double u  = m * a0 + v * a1 + q * a2 + (double)ab1[t];
    const double Phi = normcdf(u);
    const double ph  = 0.39894228040143267794 * exp(-0.5 * u * u);
    const double gp  = Phi + u * ph;
    const double gpp = (2.0 - u * u) * ph;
    const double w2  = (double)aW2[t];

    red0[t] = a0 * gp * w2;
    red1[t] = a1 * gp * w2;
    red2[t] = a2 * gp * w2;
    __syncthreads();
    if (t == 0) {
        double dm = 0, dv = 0, dq = 0;
        for (int i = 0; i < 64; ++i) { dm += red0[i]; dv += red1[i]; dq += red2[i]; }
        g_c01[2 * b]     = (float)(dm / N - 2.0 * dv * m / N1);
        g_c01[2 * b + 1] = (float)(2.0 * dv / N1 + 2.0 * dq / N);
    }
    __syncthreads();

    double quad = 0.0, Smd2 = 0.0;
    #pragma unroll
    for (int c = 0; c < 4; ++c) {
        const double md = S[2 + c] / N;
        const double qd = 2.0 * S[6 + c] / N;
        const double vd = 2.0 * (S[6 + c] - N * m * md) / N1;
        const double ud = md * a0 + vd * a1 + qd * a2;
        quad += gpp * ud * ud;
        Smd2 += md * md;
    }
    const double Smdd = S[10] / N;
    const double Sqdd = 2.0 * (S[11] + S[12]) / N;
    const double Svdd = 2.0 * (S[11] - N * Smd2 + S[12] - m * S[10]) / N1;
    const double Sudd = Smdd * a0 + Svdd * a1 + Sqdd * a2;

    red0[t] = w2 * (quad + gp * Sudd);
    __syncthreads();
    if (t == 0) {
        double L = 0.0;
        for (int i = 0; i < 64; ++i) L += red0[i];
        out[b * 4097 + 4096] = (float)L;
    }
}

// ---------------------------------------------------------------------------
// Pass C: grad = g*da + Stencil(g*db), g = c0 + c1*h.
// ---------------------------------------------------------------------------
__global__ void passC_kernel(float* __restrict__ out)
{
    const int b = blockIdx.y;
    const int s = blockIdx.x * 256 + threadIdx.x;
    const int i = s >> 6, j = s & 63;
    const int iM = (i + 63) & 63, iP = (i + 1) & 63;
    const int jM = (j + 63) & 63, jP = (j + 1) & 63;

    const float c0 = g_c01[2 * b], c1 = g_c01[2 * b + 1];
    const float* h  = g_h  + b * NS;
    const float* db = g_db + b * NS;

    const int nU = (iM << 6) | j, nD = (iP << 6) | j;
    const int nL = (i << 6) | jM, nR = (i << 6) | jP;

    const float gs = fmaf(c1, h[s], c0);
    const float st = fmaf(c1, h[nU], c0) * db[nU]
                   + fmaf(c1, h[nD], c0) * db[nD]
                   + fmaf(c1, h[nL], c0) * db[nL]
                   + fmaf(c1, h[nR], c0) * db[nR]
                   - 4.0f * gs * db[s];
    out[b * 4097 + s] = fmaf(gs, g_da[b * NS + s], st);
}

// ---------------------------------------------------------------------------
extern "C" void kernel_launch(void* const* d_in, const int* in_sizes, int n_in,
                              void* d_out, int out_size)
{
    (void)in_sizes; (void)n_in; (void)out_size;
    const float* x     = (const float*)d_in[0];
    const int*   signs = (const int*)  d_in[1];
    const float* W1    = (const float*)d_in[2];
    const float* b1    = (const float*)d_in[3];
    const float* W2    = (const float*)d_in[4];
    const float* b2    = (const float*)d_in[5];
    const float* W3    = (const float*)d_in[6];
    const float* b3    = (const float*)d_in[7];
    const float* aW1   = (const float*)d_in[8];
    const float* ab1   = (const float*)d_in[9];
    const float* aW2   = (const float*)d_in[10];
    float* out = (float*)d_out;

    cudaFuncSetAttribute(passA_mma, cudaFuncAttributeMaxDynamicSharedMemorySize, SMEMSZ);

    passA_mma<<<dim3(CPB, BATCH), 256, SMEMSZ>>>(x, signs, W1, b1, W2, b2, W3, b3);
    passB_kernel<<<BATCH, 64>>>(aW1, ab1, aW2, out);
    passC_kernel<<<dim3(16, BATCH), 256>>>(out);
}